// round 11
// baseline (speedup 1.0000x reference)
#include <cuda_runtime.h>
#include <math.h>
#include <stdint.h>

// Biquad lowpass (fs=44100, fc=10000, Q=0.707).
// R11: hybrid FIR-seed + exact IIR recursion, 8 outputs/lane, with all
// coefficients baked as compile-time immediates (FFMA-imm, rt=1, no LDC).
// Per lane: y0,y1 seeded by 12-tap truncated-FIR (trunc err ~3.8e-5 << 1e-3,
// pole mag 0.4203), then y2..y7 by the exact biquad recursion (5 FMA each).
// 54 FMA / 8 outputs vs 96 before. Warp-private 4-stage cp.async pipelines,
// zero block barriers.

#define T_LEN    160000
#define WARPS    8
#define THREADS  (WARPS * 32)
#define WTILE    256                    // outputs per warp-tile (8 per lane)
#define WHALO    16
#define WBUF_F   (WTILE + WHALO)        // 272 floats
#define WBUF_V4  (WBUF_F / 4)           // 68 float4
#define STAGES   4
#define NTW      14                     // tiles per warp
#define WSPAN    (WTILE * NTW)          // 3584
#define SPB      (WSPAN * WARPS)        // 28672 per block
#define BLOCKS_X 6                      // 6*28672 = 172032 >= 160000

// Normalized biquad coefficients (double, computed offline; cross-check:
// b0+b1+b2 = 1+a1+a2 = 1.0054575 -> DC gain exactly 1).
#define B0d 0.2513643704
#define B1d 0.5027287408
#define B2d 0.2513643704
#define A1d (-0.1712307400)
#define A2d 0.1766882000

// Truncated impulse response h[0..11], folded at compile time.
#define H0d (B0d)
#define H1d (B1d - A1d * H0d)
#define H2d (B2d - A1d * H1d - A2d * H0d)
#define H3d (-A1d * H2d - A2d * H1d)
#define H4d (-A1d * H3d - A2d * H2d)
#define H5d (-A1d * H4d - A2d * H3d)
#define H6d (-A1d * H5d - A2d * H4d)
#define H7d (-A1d * H6d - A2d * H5d)
#define H8d (-A1d * H7d - A2d * H6d)
#define H9d (-A1d * H8d - A2d * H7d)
#define H10d (-A1d * H9d - A2d * H8d)
#define H11d (-A1d * H10d - A2d * H9d)

__device__ __forceinline__ void cp_async16_cg(unsigned int saddr, const float* g, int src_bytes) {
    asm volatile("cp.async.cg.shared.global [%0], [%1], 16, %2;\n"
                 :: "r"(saddr), "l"(g), "r"(src_bytes) : "memory");
}

__global__ __launch_bounds__(THREADS) void lowpass_fir_kernel(
    const float* __restrict__ clip,
    float* __restrict__ out)
{
    __shared__ alignas(16) float buf[WARPS][STAGES][WBUF_F];

    const int tid  = threadIdx.x;
    const int warp = tid >> 5;
    const int lane = tid & 31;

    const size_t row = (size_t)blockIdx.y * T_LEN;
    const float* __restrict__ x = clip + row;
    float* __restrict__ o = out + row;

    const int strip0 = blockIdx.x * SPB + warp * WSPAN;

    const unsigned int sb0 =
        (unsigned int)__cvta_generic_to_shared(&buf[warp][0][0]);

    // Issue this warp's async copy of tile `ti` into stage (ti % STAGES).
    auto issue_tile = [&](int ti) {
        const int g = strip0 + ti * WTILE;
        const unsigned int sbase = sb0 + (unsigned int)((ti & (STAGES - 1)) * (WBUF_F * 4));
        // 68 float4: v = lane, v = 32+lane, and lanes 0-3 take v = 64+lane.
        #pragma unroll
        for (int pass = 0; pass < 2; pass++) {
            const int v = pass * 32 + lane;
            const int base = g - WHALO + 4 * v;
            const bool valid = (base >= 0) && (base <= T_LEN - 4);
            const float* gp = valid ? (x + base) : x;
            cp_async16_cg(sbase + 16u * (unsigned int)v, gp, valid ? 16 : 0);
        }
        if (lane < WBUF_V4 - 64) {
            const int v = 64 + lane;
            const int base = g - WHALO + 4 * v;
            const bool valid = (base >= 0) && (base <= T_LEN - 4);
            const float* gp = valid ? (x + base) : x;
            cp_async16_cg(sbase + 16u * (unsigned int)v, gp, valid ? 16 : 0);
        }
        asm volatile("cp.async.commit_group;\n" ::: "memory");
    };

    issue_tile(0);
    issue_tile(1);
    issue_tile(2);

    for (int i = 0; i < NTW; i++) {
        if (i + 3 < NTW) {
            asm volatile("cp.async.wait_group 2;\n" ::: "memory");  // tile i done
        } else {
            asm volatile("cp.async.wait_group 0;\n" ::: "memory");  // tail drain
        }
        __syncwarp();

        if (i + 3 < NTW) issue_tile(i + 3);  // stage already consumed (warp-sequential)

        const int g = strip0 + i * WTILE;
        const float* __restrict__ sm = &buf[warp][i & (STAGES - 1)][0];

        const int ofs = lane * 8;            // 8 outputs per lane
        const int t = g + ofs;
        if (t < T_LEN) {                     // t mult of 8, T_LEN mult of 8 -> whole chunk in
            // Window w[j] = x[t - 16 + 4 + j] ... precisely w[j] = x[t-12+j], j=0..19:
            // sm[ofs + 4 + j]; start offset mult of 4 -> 5x LDS.128.
            float w[20];
            const float4* __restrict__ w4 =
                reinterpret_cast<const float4*>(sm + ofs + 4);
            #pragma unroll
            for (int j = 0; j < 5; j++) {
                float4 v = w4[j];
                w[4 * j + 0] = v.x;
                w[4 * j + 1] = v.y;
                w[4 * j + 2] = v.z;
                w[4 * j + 3] = v.w;
            }

            // ---- FIR seeds (K=12), coefficients are immediates ----
            // y0 = sum_k h[k] * x[t-k]   = sum_k h[k] * w[12-k]
            // y1 = sum_k h[k] * x[t+1-k] = sum_k h[k] * w[13-k]
            float y0 = (float)H0d * w[12];
            float y1 = (float)H0d * w[13];
            y0 = fmaf((float)H1d,  w[11], y0);  y1 = fmaf((float)H1d,  w[12], y1);
            y0 = fmaf((float)H2d,  w[10], y0);  y1 = fmaf((float)H2d,  w[11], y1);
            y0 = fmaf((float)H3d,  w[9],  y0);  y1 = fmaf((float)H3d,  w[10], y1);
            y0 = fmaf((float)H4d,  w[8],  y0);  y1 = fmaf((float)H4d,  w[9],  y1);
            y0 = fmaf((float)H5d,  w[7],  y0);  y1 = fmaf((float)H5d,  w[8],  y1);
            y0 = fmaf((float)H6d,  w[6],  y0);  y1 = fmaf((float)H6d,  w[7],  y1);
            y0 = fmaf((float)H7d,  w[5],  y0);  y1 = fmaf((float)H7d,  w[6],  y1);
            y0 = fmaf((float)H8d,  w[4],  y0);  y1 = fmaf((float)H8d,  w[5],  y1);
            y0 = fmaf((float)H9d,  w[3],  y0);  y1 = fmaf((float)H9d,  w[4],  y1);
            y0 = fmaf((float)H10d, w[2],  y0);  y1 = fmaf((float)H10d, w[3],  y1);
            y0 = fmaf((float)H11d, w[1],  y0);  y1 = fmaf((float)H11d, w[2],  y1);

            // ---- Exact biquad recursion for y2..y7 ----
            // f_n = b0 x[t+n] + b1 x[t+n-1] + b2 x[t+n-2]  (independent)
            // y_n = f_n - a1 y_{n-1} - a2 y_{n-2}           (2-FMA chain)
            float y[8];
            y[0] = y0; y[1] = y1;
            #pragma unroll
            for (int n = 2; n < 8; n++) {
                float f = (float)B0d * w[12 + n];
                f = fmaf((float)B1d, w[11 + n], f);
                f = fmaf((float)B2d, w[10 + n], f);
                f = fmaf(-(float)A1d, y[n - 1], f);
                y[n] = fmaf(-(float)A2d, y[n - 2], f);
            }

            float4 r0, r1;
            r0.x = y[0]; r0.y = y[1]; r0.z = y[2]; r0.w = y[3];
            r1.x = y[4]; r1.y = y[5]; r1.z = y[6]; r1.w = y[7];
            float4* __restrict__ op = reinterpret_cast<float4*>(o + t);
            __stcs(op, r0);
            __stcs(op + 1, r1);
        }
        __syncwarp();
    }
}

extern "C" void kernel_launch(void* const* d_in, const int* in_sizes, int n_in,
                              void* d_out, int out_size)
{
    const float* clip = (const float*)d_in[0];
    float* out = (float*)d_out;

    const int total = in_sizes[0];
    const int batch = total / T_LEN;   // 128

    dim3 grid(BLOCKS_X, batch);        // 6 x 128 = 768 blocks, one wave
    lowpass_fir_kernel<<<grid, THREADS>>>(clip, out);
}